// round 15
// baseline (speedup 1.0000x reference)
#include <cuda_runtime.h>
#include <math.h>

#define N_NODES 8000
#define NT      (N_NODES * 12)        // 96000
#define NODES_PER_BLK 64
#define NBLOCKS 125                   // 8000/64, <=148 SMs -> all co-resident
#define NTHREADS 320

// Row-per-block partials: g_part[b][j]; rows 125..127 never written (stay 0.0
// from static zero-init) -> combine sums a fixed 128 rows in fixed order.
__device__ float    g_part[128][128];
__device__ unsigned g_arrive;         // monotonic epoch counter (never reset)

__global__ void __launch_bounds__(NTHREADS)
fused_kernel(const float* __restrict__ x,
             const float* __restrict__ U1,
             const float* __restrict__ U2,   // (5,8000) row-major
             const float* __restrict__ U3,
             const float* __restrict__ be,
             const float* __restrict__ Ve,
             const float* __restrict__ w,    // conv2_w (5,5,1,3) flat o*15+i*3+k
             const float* __restrict__ bias, // conv2_b (5,)
             float* __restrict__ out)
{
    __shared__ float sX [NODES_PER_BLK][61];      // x[nl][t*5+f], pad 61
    __shared__ float sX2[5][NODES_PER_BLK * 13];
    __shared__ float sQ[2][120];
    __shared__ float sVe[144];
    __shared__ float sBe[144];
    __shared__ float sLhs[60];
    __shared__ float sM2[60];
    __shared__ float sS[12][12];
    __shared__ float sE[12][12];
    __shared__ float sAt[12][12];
    __shared__ float sW[75];
    __shared__ float sB[5];

    const int tid = threadIdx.x;
    const int b   = blockIdx.x;
    const int n0  = b * NODES_PER_BLK;

    // ================= Pass-1: warp-specialized =================
    if (tid < 120) {
        // --- Partials straight from global: publish ASAP (no staging sync) ---
        float acc = 0.f;
        if (tid < 60) {
            const float* xp = x + n0 * 60 + tid;
            #pragma unroll 8
            for (int n = 0; n < NODES_PER_BLK; n++)
                acc += xp[n * 60] * U1[n0 + n];            // U1: broadcast/L1
        } else {
            const int jj = tid - 60;
            const int f2 = jj / 12, t = jj % 12;
            float u3[5];
            #pragma unroll
            for (int f = 0; f < 5; f++) u3[f] = U3[f];
            const float* xp = x + n0 * 60 + t * 5;
            const float* u2 = U2 + f2 * N_NODES + n0;
            #pragma unroll 8
            for (int n = 0; n < NODES_PER_BLK; n++) {
                float r = 0.f;
                #pragma unroll
                for (int f = 0; f < 5; f++) r += xp[n * 60 + f] * u3[f];
                acc += u2[n] * r;                          // same L1 lines as above
            }
        }
        g_part[b][tid] = acc;                              // coalesced row
    } else {
        // --- Loader warps: x tile + all small tensors (hidden under barrier) ---
        const int lt = tid - 128;                          // may be <0 for 120..127
        if (lt >= 0) {
            const float4* xp = (const float4*)(x + n0 * 60);
            #pragma unroll
            for (int r = 0; r < 5; r++) {
                const int j = lt + r * 192;                // 0..959
                float4 v = xp[j];
                const int n = j / 15, c = (j % 15) * 4;
                float* d = &sX[n][c];
                d[0] = v.x; d[1] = v.y; d[2] = v.z; d[3] = v.w;
            }
            if (lt < 144)      sVe[lt]      = Ve[lt];
            if (lt < 144)      sBe[lt]      = be[lt];
            if (lt < 75)       sW[lt]       = w[lt];
            if (lt < 5)        sB[lt]       = bias[lt];
        }
    }

    // Release partials + arrive. Only warp0's lane0 fences/spins; the STG from
    // threads 0..119 happened in the same warps pre-sync? No: g_part stores are
    // by threads 0..119 (warps 0..3). A named sync of those warps orders them
    // before tid0's fence. Use bar 1 scoped to 128 threads (warps 0..3).
    if (tid < 128) {
        asm volatile("bar.sync 1, 128;" ::: "memory");     // order warps 0..3 STGs
        if (tid == 0) {
            __threadfence();                               // release partials
            unsigned old = atomicAdd(&g_arrive, 1u);
            const unsigned target =
                (old / (unsigned)NBLOCKS + 1u) * (unsigned)NBLOCKS;
            volatile unsigned* va = &g_arrive;
            while (*va < target) __nanosleep(128);
            __threadfence();                               // acquire
        }
    }
    __syncthreads();    // joins loaders + spinners; all shared + g_part visible

    // ---- Combine: (half q, j) sums 64 fixed rows, 4 independent chains ----
    if (tid < 240) {
        const int q = tid / 120, j = tid % 120;
        const float* p = &g_part[q * 64][0];
        float a0 = 0.f, a1 = 0.f, a2 = 0.f, a3 = 0.f;
        #pragma unroll
        for (int i = 0; i < 64; i += 4) {                  // rows 125..127 are 0
            a0 += __ldcg(p + (i + 0) * 128 + j);
            a1 += __ldcg(p + (i + 1) * 128 + j);
            a2 += __ldcg(p + (i + 2) * 128 + j);
            a3 += __ldcg(p + (i + 3) * 128 + j);
        }
        sQ[q][j] = (a0 + a1) + (a2 + a3);                  // fixed order
    }
    __syncthreads();
    if (tid < 120) {
        float s = sQ[0][tid] + sQ[1][tid];
        if (tid < 60) sLhs[tid] = s;
        else          sM2[tid - 60] = s;
    }
    __syncthreads();

    // ---- At2 distributed: 144-thread phases ----
    if (tid < 144) {
        const int t1 = tid / 12, t2 = tid % 12;
        float p = 0.f;
        #pragma unroll
        for (int f = 0; f < 5; f++) p += sLhs[t1 * 5 + f] * sM2[f * 12 + t2];
        p += sBe[tid];
        sS[t1][t2] = 1.f / (1.f + __expf(-p));
    }
    __syncthreads();
    if (tid < 144) {
        const int t1 = tid / 12, t2 = tid % 12;
        float e = 0.f;
        #pragma unroll
        for (int k = 0; k < 12; k++) e += sVe[t1 * 12 + k] * sS[k][t2];
        sE[t1][t2] = e;
    }
    __syncthreads();
    if (tid < 12) {                                        // column softmax
        const int t2 = tid;
        float E[12];
        float mx = -1e30f;
        #pragma unroll
        for (int k = 0; k < 12; k++) { E[k] = sE[k][t2]; mx = fmaxf(mx, E[k]); }
        float den = 0.f;
        #pragma unroll
        for (int k = 0; k < 12; k++) { E[k] = __expf(E[k] - mx); den += E[k]; }
        const float inv = 1.f / den;
        #pragma unroll
        for (int k = 0; k < 12; k++) sAt[k][t2] = E[k] * inv;
    }
    __syncthreads();

    // ---- Phase B: thread (f, nl) -> x2[f][nl][0..11] ----
    {
        const int f  = tid / NODES_PER_BLK;
        const int nl = tid % NODES_PER_BLK;
        float xr[12];
        #pragma unroll
        for (int tp = 0; tp < 12; tp++) xr[tp] = sX[nl][tp * 5 + f];
        float* dst = &sX2[f][nl * 13];
        #pragma unroll
        for (int t = 0; t < 12; t++) {
            float a = 0.f;
            #pragma unroll
            for (int tp = 0; tp < 12; tp++) a += xr[tp] * sAt[tp][t];
            dst[t] = a;
        }
    }
    __syncthreads();

    // ---- Phase C: thread (o, nl) -> conv plane + coalesced 48B store ----
    {
        const int o  = tid / NODES_PER_BLK;
        const int nl = tid % NODES_PER_BLK;
        float wr[15];
        #pragma unroll
        for (int i = 0; i < 15; i++) wr[i] = sW[o * 15 + i];
        const float b0 = sB[o];

        float yr[12];
        #pragma unroll
        for (int t = 0; t < 12; t++) yr[t] = b0;
        #pragma unroll
        for (int fi = 0; fi < 5; fi++) {
            const float* s = &sX2[fi][nl * 13];
            float v[12];
            #pragma unroll
            for (int t = 0; t < 12; t++) v[t] = s[t];
            const float w0 = wr[fi * 3 + 0], w1 = wr[fi * 3 + 1], w2 = wr[fi * 3 + 2];
            #pragma unroll
            for (int t = 0; t < 12; t++) {
                float a = w1 * v[t];
                if (t > 0)  a += w0 * v[t - 1];
                if (t < 11) a += w2 * v[t + 1];
                yr[t] += a;
            }
        }
        // raw-reshape output: flat = o*N*T + n*T + t
        float4* op = (float4*)(out + o * NT + (n0 + nl) * 12);
        op[0] = make_float4(yr[0], yr[1], yr[2],  yr[3]);
        op[1] = make_float4(yr[4], yr[5], yr[6],  yr[7]);
        op[2] = make_float4(yr[8], yr[9], yr[10], yr[11]);
    }
}

extern "C" void kernel_launch(void* const* d_in, const int* in_sizes, int n_in,
                              void* d_out, int out_size)
{
    // metadata order: x, adj, U1_1, U2_1, U3_1, be_1, Ve_1,
    //                 U1_2, U2_2, U3_2, be_2, Ve_2,
    //                 conv1_w, conv1_b, conv2_w, conv2_b, W_hgc, b_hgc
    const float* x    = (const float*)d_in[0];
    const float* U1_2 = (const float*)d_in[7];
    const float* U2_2 = (const float*)d_in[8];
    const float* U3_2 = (const float*)d_in[9];
    const float* be_2 = (const float*)d_in[10];
    const float* Ve_2 = (const float*)d_in[11];
    const float* c2w  = (const float*)d_in[14];
    const float* c2b  = (const float*)d_in[15];
    float* out = (float*)d_out;

    // Hyperbolic branch contributes exactly 0.0*finite -> skipped entirely.
    fused_kernel<<<NBLOCKS, NTHREADS>>>(x, U1_2, U2_2, U3_2, be_2, Ve_2, c2w, c2b, out);
}

// round 16
// speedup vs baseline: 1.3747x; 1.3747x over previous
#include <cuda_runtime.h>
#include <math.h>

#define N_NODES 8000
#define NT      (N_NODES * 12)        // 96000
#define NODES_PER_BLK 64
#define NBLOCKS 125                   // 8000/64, <=148 SMs -> all co-resident
#define NTHREADS 320

// Row-per-block partials: g_part[b][j]; rows 125..127 never written (stay 0.0
// from static zero-init) -> combine sums a fixed 128 rows in fixed order.
__device__ float    g_part[128][128];
__device__ unsigned g_arrive;         // monotonic epoch counter (never reset)

__global__ void __launch_bounds__(NTHREADS)
fused_kernel(const float* __restrict__ x,
             const float* __restrict__ U1,
             const float* __restrict__ U2,   // (5,8000) row-major
             const float* __restrict__ U3,
             const float* __restrict__ be,
             const float* __restrict__ Ve,
             const float* __restrict__ w,    // conv2_w (5,5,1,3) flat o*15+i*3+k
             const float* __restrict__ bias, // conv2_b (5,)
             float* __restrict__ out)
{
    __shared__ float sX [NODES_PER_BLK][61];      // x[nl][t*5+f], pad 61
    __shared__ float sX2[5][NODES_PER_BLK * 13];
    __shared__ float sQ[2][120];
    __shared__ float sUU[384];                    // [0..63]=U1 tile, [64..383]=U2 tile
    __shared__ float sVe[144];
    __shared__ float sBe[144];
    __shared__ float sLhs[60];
    __shared__ float sM2[60];
    __shared__ float sS[12][12];
    __shared__ float sE[12][12];
    __shared__ float sAt[12][12];
    __shared__ float sW[75];
    __shared__ float sB[5];

    const int tid = threadIdx.x;
    const int b   = blockIdx.x;
    const int n0  = b * NODES_PER_BLK;

    // ============ Pass-1: producer/consumer pipeline ============
    if (tid >= 128) {
        // ---- Loaders (192 threads): 5 float4 each, all LDGs in flight ----
        const int lt = tid - 128;                 // 0..191
        const float4* xp = (const float4*)(x + n0 * 60);
        float4 v0 = xp[lt];
        float4 v1 = xp[lt + 192];
        float4 v2 = xp[lt + 384];
        float4 v3 = xp[lt + 576];
        float4 v4 = xp[lt + 768];

        #define HX_STORE(vv, jj) do {                                   \
            const int _n = (jj) / 15, _c = ((jj) % 15) * 4;             \
            float* _d = &sX[_n][_c];                                    \
            _d[0] = (vv).x; _d[1] = (vv).y; _d[2] = (vv).z; _d[3] = (vv).w; } while (0)

        HX_STORE(v0, lt);       __threadfence_block();
        asm volatile("bar.arrive 1, 320;" ::: "memory");
        HX_STORE(v1, lt + 192); __threadfence_block();
        asm volatile("bar.arrive 2, 320;" ::: "memory");
        HX_STORE(v2, lt + 384); __threadfence_block();
        asm volatile("bar.arrive 3, 320;" ::: "memory");
        HX_STORE(v3, lt + 576); __threadfence_block();
        asm volatile("bar.arrive 4, 320;" ::: "memory");
        HX_STORE(v4, lt + 768); __threadfence_block();
        asm volatile("bar.arrive 5, 320;" ::: "memory");
        #undef HX_STORE

        // small tensors: hidden under the grid-barrier spin
        if (lt < 144) sVe[lt] = Ve[lt];
        if (lt < 144) sBe[lt] = be[lt];
        if (lt < 75)  sW[lt]  = w[lt];
        if (lt < 5)   sB[lt]  = bias[lt];
    } else {
        // ---- Partial group (threads 0..127; 0..119 active) ----
        if (tid < 120) {
            #pragma unroll
            for (int k = 0; k < 4; k++) {
                const int idx = tid + 120 * k;
                if (idx < 384) {
                    float v;
                    if (idx < 64) v = U1[n0 + idx];
                    else {
                        const int q = idx - 64;
                        v = U2[(q >> 6) * N_NODES + n0 + (q & 63)];
                    }
                    sUU[idx] = v;
                }
            }
        }
        float u3[5];
        if (tid >= 60 && tid < 120) {
            #pragma unroll
            for (int f = 0; f < 5; f++) u3[f] = __ldg(&U3[f]);
        }
        asm volatile("bar.sync 7, 128;" ::: "memory");    // sUU ready (group-local)

        // node counts completed after round r: floor(192*(r+1)/15)
        const int nb[6] = {0, 12, 25, 38, 51, 64};
        float acc = 0.f;
        const int jj = tid - 60;
        const int f2 = jj / 12, t = jj % 12;              // valid for 60<=tid<120
        #pragma unroll
        for (int r = 0; r < 5; r++) {
            asm volatile("bar.sync %0, 320;" :: "r"(1 + r) : "memory");
            if (tid < 60) {
                for (int n = nb[r]; n < nb[r + 1]; n++)
                    acc += sX[n][tid] * sUU[n];           // node order 0..63: same as champion
            } else if (tid < 120) {
                for (int n = nb[r]; n < nb[r + 1]; n++) {
                    float rr = 0.f;
                    #pragma unroll
                    for (int f = 0; f < 5; f++) rr += sX[n][t * 5 + f] * u3[f];
                    acc += sUU[64 + f2 * 64 + n] * rr;
                }
            }
        }
        if (tid < 120) g_part[b][tid] = acc;              // coalesced row
        asm volatile("bar.sync 6, 128;" ::: "memory");    // order STGs before fence

        // ---- Grid barrier: single release fence + backoff spin ----
        if (tid == 0) {
            __threadfence();                              // release partials
            unsigned old = atomicAdd(&g_arrive, 1u);
            const unsigned target =
                (old / (unsigned)NBLOCKS + 1u) * (unsigned)NBLOCKS;
            volatile unsigned* va = &g_arrive;
            while (*va < target) __nanosleep(128);
            __threadfence();                              // acquire
        }
    }
    __syncthreads();    // rejoin all roles; shared + g_part visible everywhere

    // ---- Combine: (half q, j) sums 64 fixed rows, 4 independent chains ----
    if (tid < 240) {
        const int q = tid / 120, j = tid % 120;
        const float* p = &g_part[q * 64][0];
        float a0 = 0.f, a1 = 0.f, a2 = 0.f, a3 = 0.f;
        #pragma unroll
        for (int i = 0; i < 64; i += 4) {                 // rows 125..127 are 0
            a0 += __ldcg(p + (i + 0) * 128 + j);
            a1 += __ldcg(p + (i + 1) * 128 + j);
            a2 += __ldcg(p + (i + 2) * 128 + j);
            a3 += __ldcg(p + (i + 3) * 128 + j);
        }
        sQ[q][j] = (a0 + a1) + (a2 + a3);                 // fixed order
    }
    __syncthreads();
    if (tid < 120) {
        float s = sQ[0][tid] + sQ[1][tid];
        if (tid < 60) sLhs[tid] = s;
        else          sM2[tid - 60] = s;
    }
    __syncthreads();

    // ---- At2 distributed: 144-thread phases ----
    if (tid < 144) {
        const int t1 = tid / 12, t2 = tid % 12;
        float p = 0.f;
        #pragma unroll
        for (int f = 0; f < 5; f++) p += sLhs[t1 * 5 + f] * sM2[f * 12 + t2];
        p += sBe[tid];
        sS[t1][t2] = 1.f / (1.f + __expf(-p));
    }
    __syncthreads();
    if (tid < 144) {
        const int t1 = tid / 12, t2 = tid % 12;
        float e = 0.f;
        #pragma unroll
        for (int k = 0; k < 12; k++) e += sVe[t1 * 12 + k] * sS[k][t2];
        sE[t1][t2] = e;
    }
    __syncthreads();
    if (tid < 12) {                                       // column softmax
        const int t2 = tid;
        float E[12];
        float mx = -1e30f;
        #pragma unroll
        for (int k = 0; k < 12; k++) { E[k] = sE[k][t2]; mx = fmaxf(mx, E[k]); }
        float den = 0.f;
        #pragma unroll
        for (int k = 0; k < 12; k++) { E[k] = __expf(E[k] - mx); den += E[k]; }
        const float inv = 1.f / den;
        #pragma unroll
        for (int k = 0; k < 12; k++) sAt[k][t2] = E[k] * inv;
    }
    __syncthreads();

    // ---- Phase B: thread (f, nl) -> x2[f][nl][0..11] ----
    {
        const int f  = tid / NODES_PER_BLK;
        const int nl = tid % NODES_PER_BLK;
        float xr[12];
        #pragma unroll
        for (int tp = 0; tp < 12; tp++) xr[tp] = sX[nl][tp * 5 + f];
        float* dst = &sX2[f][nl * 13];
        #pragma unroll
        for (int t = 0; t < 12; t++) {
            float a = 0.f;
            #pragma unroll
            for (int tp = 0; tp < 12; tp++) a += xr[tp] * sAt[tp][t];
            dst[t] = a;
        }
    }
    __syncthreads();

    // ---- Phase C: thread (o, nl) -> conv plane + coalesced 48B store ----
    {
        const int o  = tid / NODES_PER_BLK;
        const int nl = tid % NODES_PER_BLK;
        float wr[15];
        #pragma unroll
        for (int i = 0; i < 15; i++) wr[i] = sW[o * 15 + i];
        const float b0 = sB[o];

        float yr[12];
        #pragma unroll
        for (int t = 0; t < 12; t++) yr[t] = b0;
        #pragma unroll
        for (int fi = 0; fi < 5; fi++) {
            const float* s = &sX2[fi][nl * 13];
            float v[12];
            #pragma unroll
            for (int t = 0; t < 12; t++) v[t] = s[t];
            const float w0 = wr[fi * 3 + 0], w1 = wr[fi * 3 + 1], w2 = wr[fi * 3 + 2];
            #pragma unroll
            for (int t = 0; t < 12; t++) {
                float a = w1 * v[t];
                if (t > 0)  a += w0 * v[t - 1];
                if (t < 11) a += w2 * v[t + 1];
                yr[t] += a;
            }
        }
        // raw-reshape output: flat = o*N*T + n*T + t
        float4* op = (float4*)(out + o * NT + (n0 + nl) * 12);
        op[0] = make_float4(yr[0], yr[1], yr[2],  yr[3]);
        op[1] = make_float4(yr[4], yr[5], yr[6],  yr[7]);
        op[2] = make_float4(yr[8], yr[9], yr[10], yr[11]);
    }
}

extern "C" void kernel_launch(void* const* d_in, const int* in_sizes, int n_in,
                              void* d_out, int out_size)
{
    // metadata order: x, adj, U1_1, U2_1, U3_1, be_1, Ve_1,
    //                 U1_2, U2_2, U3_2, be_2, Ve_2,
    //                 conv1_w, conv1_b, conv2_w, conv2_b, W_hgc, b_hgc
    const float* x    = (const float*)d_in[0];
    const float* U1_2 = (const float*)d_in[7];
    const float* U2_2 = (const float*)d_in[8];
    const float* U3_2 = (const float*)d_in[9];
    const float* be_2 = (const float*)d_in[10];
    const float* Ve_2 = (const float*)d_in[11];
    const float* c2w  = (const float*)d_in[14];
    const float* c2b  = (const float*)d_in[15];
    float* out = (float*)d_out;

    // Hyperbolic branch contributes exactly 0.0*finite -> skipped entirely.
    fused_kernel<<<NBLOCKS, NTHREADS>>>(x, U1_2, U2_2, U3_2, be_2, Ve_2, c2w, c2b, out);
}